// round 15
// baseline (speedup 1.0000x reference)
#include <cuda_runtime.h>
#include <cuda_bf16.h>

#define N_NODES 100000
#define D_IN    2048
#define H_DIM   50
#define C_CLS   6
#define M_EDGES 3200000
#define L_LAYERS 3
#define CAP     128          // per-node per-direction edge capacity (mean deg 32)
#define KC      64           // gemm1 K-chunk
#define NT      7            // n-tiles (7*8 = 56 >= 50)

// ---------------- scratch (device globals; no allocation allowed) ----------
__device__ __align__(16) float2 g_LX[CAP * N_NODES];   // slot-major: [slot][node] = {other, v}
__device__ __align__(16) float2 g_LY[CAP * N_NODES];
__device__ int g_cX[N_NODES];
__device__ int g_cY[N_NODES];
__device__ __align__(16) float g_x1[N_NODES * H_DIM];  // layer-1 activations
__device__ __align__(16) float g_z [N_NODES * 8];      // z padded to 8 floats/row
__device__ __align__(16) float g_EmB[2 * N_NODES * 8]; // e^{-z}, double-buffered
__device__ __align__(16) float g_EpB[2 * N_NODES * 8]; // e^{+z}, double-buffered
// W1 in pre-permuted mma-fragment layout: [s=128][n=56][tg=4] x uint4
// uint4 = {bh(k0,k0+1), bh(k0+8,k0+9), bl(k0,k0+1), bl(k0+8,k0+9)}, k0=16s+2tg
__device__ __align__(16) uint4 g_W1p[128 * NT * 8 * 4];

typedef unsigned long long ull;

__device__ __forceinline__ ull pack2(float x, float y) {
    ull r; asm("mov.b64 %0, {%1, %2};" : "=l"(r) : "f"(x), "f"(y)); return r;
}
__device__ __forceinline__ void unpack2(ull v, float& x, float& y) {
    asm("mov.b64 {%0, %1}, %2;" : "=f"(x), "=f"(y) : "l"(v));
}
__device__ __forceinline__ ull ffma2(ull a, ull b, ull c) {
    ull d; asm("fma.rn.f32x2 %0, %1, %2, %3;" : "=l"(d) : "l"(a), "l"(b), "l"(c)); return d;
}
__device__ __forceinline__ float rcpa(float x) {
    float r; asm("rcp.approx.f32 %0, %1;" : "=f"(r) : "f"(x)); return r;
}
// pack two f32 -> bf16x2 (x1 -> high half, x0 -> low half)
__device__ __forceinline__ unsigned int cvt_bf16x2(float x1, float x0) {
    unsigned int r;
    asm("cvt.rn.bf16x2.f32 %0, %1, %2;" : "=r"(r) : "f"(x1), "f"(x0));
    return r;
}
// split float2 into hi bf16x2 and residual-lo bf16x2
__device__ __forceinline__ void split2(float2 x, unsigned int& h, unsigned int& l) {
    h = cvt_bf16x2(x.y, x.x);
    float l0 = x.x - __uint_as_float(h << 16);
    float l1 = x.y - __uint_as_float(h & 0xffff0000u);
    l = cvt_bf16x2(l1, l0);
}
__device__ __forceinline__ void mma16816(float* d,
    unsigned int a0, unsigned int a1, unsigned int a2, unsigned int a3,
    unsigned int b0, unsigned int b1)
{
    asm volatile(
        "mma.sync.aligned.m16n8k16.row.col.f32.bf16.bf16.f32 "
        "{%0,%1,%2,%3}, {%4,%5,%6,%7}, {%8,%9}, {%0,%1,%2,%3};"
        : "+f"(d[0]), "+f"(d[1]), "+f"(d[2]), "+f"(d[3])
        : "r"(a0), "r"(a1), "r"(a2), "r"(a3), "r"(b0), "r"(b1));
}
__device__ __forceinline__ void cp_async16(unsigned int smem_dst, const void* gsrc) {
    asm volatile("cp.async.cg.shared.global [%0], [%1], 16;" :: "r"(smem_dst), "l"(gsrc));
}

// ---------------- K-2: W1 -> permuted bf16 hi/lo fragment layout ----------
// linear idx = s*(NT*8*4) + n*4 + tg,  n in [0,56), k0 = 16s + 2tg
__global__ void w1split_kernel(const float* __restrict__ W1) {
    int idx = blockIdx.x * 256 + threadIdx.x;
    if (idx >= 128 * NT * 8 * 4) return;
    int tg = idx & 3;
    int n  = (idx >> 2) % (NT * 8);
    int s  = idx / (NT * 8 * 4);
    int k0 = s * 16 + 2 * tg;
    unsigned short h[4], l[4];
#pragma unroll
    for (int j = 0; j < 4; j++) {
        int k = k0 + (j >> 1) * 8 + (j & 1);    // k0, k0+1, k0+8, k0+9
        float w = (n < H_DIM) ? W1[k * H_DIM + n] : 0.f;
        __nv_bfloat16 hb = __float2bfloat16(w);
        float hf = __bfloat162float(hb);
        __nv_bfloat16 lb = __float2bfloat16(w - hf);
        h[j] = __bfloat16_as_ushort(hb);
        l[j] = __bfloat16_as_ushort(lb);
    }
    uint4 v;
    v.x = (unsigned int)h[0] | ((unsigned int)h[1] << 16);
    v.y = (unsigned int)h[2] | ((unsigned int)h[3] << 16);
    v.z = (unsigned int)l[0] | ((unsigned int)l[1] << 16);
    v.w = (unsigned int)l[2] | ((unsigned int)l[3] << 16);
    g_W1p[idx] = v;
}

// ---------------- K-1: zero the CSR counters ------------------------------
__global__ void zero_kernel() {
    int n = blockIdx.x * 256 + threadIdx.x;
    if (n < N_NODES) { g_cX[n] = 0; g_cY[n] = 0; }
}

// ---------------- K0: bucket edges into pull lists ------------------------
__global__ void prep_kernel(const float* __restrict__ rel,
                            const int* __restrict__ sx,
                            const int* __restrict__ sy) {
    int m = blockIdx.x * 256 + threadIdx.x;
    if (m >= M_EDGES) return;
    int a = sx[m], b = sy[m];
    float v = __expf(-rel[m]);
    int ix = atomicAdd(&g_cX[a], 1);
    if (ix < CAP) g_LX[(size_t)ix * N_NODES + a] = make_float2(__int_as_float(b), v);
    int iy = atomicAdd(&g_cY[b], 1);
    if (iy < CAP) g_LY[(size_t)iy * N_NODES + b] = make_float2(__int_as_float(a), v);
}

// ---------------- K1: x1 = relu(F @ W1 + b1), bf16-split MMA v4 ----------
// 128 thr / 4 warps / m32 per warp / 128 rows per CTA, target 4 CTAs/SM.
// n-tiles = 7 (56 cols): 42 MMAs + 7 LDS.128 per s-step per warp.
// A: LDG float2 temps -> MMAs on current split regs -> split temps in place.
// B: pre-permuted frag layout, cp.async double-buffered 14KB chunks.
__global__ __launch_bounds__(128, 4) void gemm1_mma_kernel(
    const float* __restrict__ F, const float* __restrict__ b1)
{
    __shared__ __align__(16) uint4 sB[2][4 * NT * 8 * 4];   // 14KB per buf

    const int CHW = 4 * NT * 8 * 4;   // uint4 per chunk = 896
    int tid  = threadIdx.x;
    int n0   = blockIdx.x * 128;
    int lane = tid & 31, wid = tid >> 5;
    int g = lane >> 2, tg = lane & 3;

    int r0 = n0 + wid * 32 + g;
    bool ok[4] = { r0 < N_NODES, r0 + 8 < N_NODES, r0 + 16 < N_NODES, r0 + 24 < N_NODES };
    const float* Fr[4] = {
        F + (size_t)(r0     ) * D_IN, F + (size_t)(r0 + 8 ) * D_IN,
        F + (size_t)(r0 + 16) * D_IN, F + (size_t)(r0 + 24) * D_IN };

    // stage B chunk 0 (896 uint4 = 7 per thread)
#pragma unroll
    for (int i = 0; i < 7; i++) {
        int x = i * 128 + tid;
        cp_async16((unsigned int)__cvta_generic_to_shared(&sB[0][x]), g_W1p + x);
    }
    asm volatile("cp.async.commit_group;");

    // current A split regs, loaded for s=0
    unsigned int aH[2][4], aL[2][4];
    float2 zf = make_float2(0.f, 0.f);
#pragma unroll
    for (int t = 0; t < 2; t++)
#pragma unroll
        for (int j = 0; j < 2; j++) {
            float2 x0 = ok[t * 2 + j] ? *(const float2*)(Fr[t * 2 + j] + 2 * tg)     : zf;
            float2 x1 = ok[t * 2 + j] ? *(const float2*)(Fr[t * 2 + j] + 2 * tg + 8) : zf;
            split2(x0, aH[t][j],     aL[t][j]);
            split2(x1, aH[t][j + 2], aL[t][j + 2]);
        }

    float d[2][NT][4];
#pragma unroll
    for (int t = 0; t < 2; t++)
#pragma unroll
        for (int nt = 0; nt < NT; nt++)
#pragma unroll
            for (int j = 0; j < 4; j++) d[t][nt][j] = 0.f;

    asm volatile("cp.async.wait_group 0;");
    __syncthreads();

    int p = 0;
    for (int kc = 0; kc < D_IN; kc += KC) {
        int kn = kc + KC;
        if (kn < D_IN) {     // prefetch next B chunk into buf p^1
            const uint4* src = g_W1p + (kn >> 4) * (NT * 8 * 4);
#pragma unroll
            for (int i = 0; i < 7; i++) {
                int x = i * 128 + tid;
                cp_async16((unsigned int)__cvta_generic_to_shared(&sB[p ^ 1][x]), src + x);
            }
            asm volatile("cp.async.commit_group;");
        }

        const uint4* bp = sB[p];
#pragma unroll
        for (int s = 0; s < 4; s++) {
            // 1) issue LDGs for next s-step into temps
            int cnext = (s < 3) ? (kc + (s + 1) * 16 + 2 * tg)
                                : ((kn < D_IN) ? (kn + 2 * tg) : (kc + 2 * tg));
            float2 t00 = ok[0] ? *(const float2*)(Fr[0] + cnext)     : zf;
            float2 t01 = ok[1] ? *(const float2*)(Fr[1] + cnext)     : zf;
            float2 t02 = ok[0] ? *(const float2*)(Fr[0] + cnext + 8) : zf;
            float2 t03 = ok[1] ? *(const float2*)(Fr[1] + cnext + 8) : zf;
            float2 t10 = ok[2] ? *(const float2*)(Fr[2] + cnext)     : zf;
            float2 t11 = ok[3] ? *(const float2*)(Fr[3] + cnext)     : zf;
            float2 t12 = ok[2] ? *(const float2*)(Fr[2] + cnext + 8) : zf;
            float2 t13 = ok[3] ? *(const float2*)(Fr[3] + cnext + 8) : zf;

            // 2) MMAs on current split regs (LDG latency covered here)
#pragma unroll
            for (int nt = 0; nt < NT; nt++) {
                uint4 bb = bp[s * (NT * 8 * 4) + (nt * 8 + g) * 4 + tg];  // LDS.128
#pragma unroll
                for (int t = 0; t < 2; t++) {
                    mma16816(d[t][nt], aH[t][0], aH[t][1], aH[t][2], aH[t][3], bb.x, bb.y);
                    mma16816(d[t][nt], aH[t][0], aH[t][1], aH[t][2], aH[t][3], bb.z, bb.w);
                    mma16816(d[t][nt], aL[t][0], aL[t][1], aL[t][2], aL[t][3], bb.x, bb.y);
                }
            }

            // 3) split temps into current regs for next step
            split2(t00, aH[0][0], aL[0][0]);
            split2(t01, aH[0][1], aL[0][1]);
            split2(t02, aH[0][2], aL[0][2]);
            split2(t03, aH[0][3], aL[0][3]);
            split2(t10, aH[1][0], aL[1][0]);
            split2(t11, aH[1][1], aL[1][1]);
            split2(t12, aH[1][2], aL[1][2]);
            split2(t13, aH[1][3], aL[1][3]);
        }

        if (kn < D_IN) { asm volatile("cp.async.wait_group 0;"); }
        __syncthreads();
        p ^= 1;
    }

    // ---- epilogue: bias + relu -> g_x1 [node][50] ----
#pragma unroll
    for (int t = 0; t < 2; t++) {
        int row0 = n0 + wid * 32 + t * 16 + g;
#pragma unroll
        for (int nt = 0; nt < NT; nt++) {
            int col = nt * 8 + 2 * tg;
            if (col < H_DIM) {        // 50 even: float2 pairs never straddle
                float bb0 = __ldg(&b1[col]), bb1 = __ldg(&b1[col + 1]);
                if (row0 < N_NODES) {
                    float2 o = make_float2(fmaxf(d[t][nt][0] + bb0, 0.f),
                                           fmaxf(d[t][nt][1] + bb1, 0.f));
                    *(float2*)&g_x1[(size_t)row0 * H_DIM + col] = o;
                }
                int row1 = row0 + 8;
                if (row1 < N_NODES) {
                    float2 o = make_float2(fmaxf(d[t][nt][2] + bb0, 0.f),
                                           fmaxf(d[t][nt][3] + bb1, 0.f));
                    *(float2*)&g_x1[(size_t)row1 * H_DIM + col] = o;
                }
            }
        }
    }
}

// ---------------- K2: fused layers 2..4 -> z + initial exp tables ---------
__global__ __launch_bounds__(128) void mlp_tail_kernel(
    const float* __restrict__ W2, const float* __restrict__ b2,
    const float* __restrict__ W3, const float* __restrict__ b3,
    const float* __restrict__ W4, const float* __restrict__ b4)
{
    __shared__ __align__(16) float sW2[2500];
    __shared__ __align__(16) float sW3[2500];
    __shared__ __align__(16) float sW4[304];
    __shared__ float sB2[56], sB3[56], sB4[8];

    int tid = threadIdx.x;
    for (int i = tid; i < 2500; i += 128) { sW2[i] = W2[i]; sW3[i] = W3[i]; }
    for (int i = tid; i < 300;  i += 128) sW4[i] = W4[i];
    if (tid < 50) { sB2[tid] = b2[tid]; sB3[tid] = b3[tid]; }
    if (tid < 6)  sB4[tid] = b4[tid];
    __syncthreads();

    int node = blockIdx.x * 128 + tid;
    if (node >= N_NODES) return;

    float xa[50];
    const float* xin = &g_x1[(size_t)node * H_DIM];
#pragma unroll
    for (int j = 0; j < 25; j++) {
        float2 v = *(const float2*)(xin + 2 * j);
        xa[2 * j] = v.x; xa[2 * j + 1] = v.y;
    }

    // layer 2
    {
        ull acc[25];
#pragma unroll
        for (int j = 0; j < 25; j++) acc[j] = 0ull;
#pragma unroll
        for (int k = 0; k < 50; k++) {
            ull f2 = pack2(xa[k], xa[k]);
            const float* wr = &sW2[k * 50];
#pragma unroll
            for (int j = 0; j < 25; j++)
                acc[j] = ffma2(f2, *(const ull*)(wr + 2 * j), acc[j]);
        }
#pragma unroll
        for (int j = 0; j < 25; j++) {
            float a, b; unpack2(acc[j], a, b);
            xa[2 * j]     = fmaxf(a + sB2[2 * j],     0.f);
            xa[2 * j + 1] = fmaxf(b + sB2[2 * j + 1], 0.f);
        }
    }
    // layer 3
    {
        ull acc[25];
#pragma unroll
        for (int j = 0; j < 25; j++) acc[j] = 0ull;
#pragma unroll
        for (int k = 0; k < 50; k++) {
            ull f2 = pack2(xa[k], xa[k]);
            const float* wr = &sW3[k * 50];
#pragma unroll
            for (int j = 0; j < 25; j++)
                acc[j] = ffma2(f2, *(const ull*)(wr + 2 * j), acc[j]);
        }
#pragma unroll
        for (int j = 0; j < 25; j++) {
            float a, b; unpack2(acc[j], a, b);
            xa[2 * j]     = fmaxf(a + sB3[2 * j],     0.f);
            xa[2 * j + 1] = fmaxf(b + sB3[2 * j + 1], 0.f);
        }
    }
    // layer 4 -> z, plus exp tables for KENN layer 0 (buffer 0)
    {
        ull acc[3] = {0ull, 0ull, 0ull};
#pragma unroll
        for (int k = 0; k < 50; k++) {
            ull f2 = pack2(xa[k], xa[k]);
            const float* wr = &sW4[k * 6];
#pragma unroll
            for (int j = 0; j < 3; j++)
                acc[j] = ffma2(f2, *(const ull*)(wr + 2 * j), acc[j]);
        }
        float zr[6];
#pragma unroll
        for (int j = 0; j < 3; j++) {
            float a, b; unpack2(acc[j], a, b);
            zr[2 * j]     = a + sB4[2 * j];
            zr[2 * j + 1] = b + sB4[2 * j + 1];
        }
        float* zp = &g_z[(size_t)node * 8];
        *(float4*)zp       = make_float4(zr[0], zr[1], zr[2], zr[3]);
        *(float2*)(zp + 4) = make_float2(zr[4], zr[5]);

        float em[6], ep[6];
#pragma unroll
        for (int c = 0; c < 6; c++) { ep[c] = __expf(zr[c]); em[c] = __expf(-zr[c]); }
        float* e1 = &g_EmB[(size_t)node * 8];
        float* e2 = &g_EpB[(size_t)node * 8];
        *(float4*)e1       = make_float4(em[0], em[1], em[2], em[3]);
        *(float2*)(e1 + 4) = make_float2(em[4], em[5]);
        *(float4*)e2       = make_float4(ep[0], ep[1], ep[2], ep[3]);
        *(float2*)(e2 + 4) = make_float2(ep[4], ep[5]);
    }
}

// ---------------- K3: KENN layer, pull-based (no atomics) -----------------
__global__ __launch_bounds__(256) void layer_kernel(
    const float* __restrict__ cw, int rd, int last, float* __restrict__ out)
{
    int n = blockIdx.x * 256 + threadIdx.x;
    if (n >= N_NODES) return;

    const float* EmR = g_EmB + (size_t)rd * N_NODES * 8;
    const float* EpR = g_EpB + (size_t)rd * N_NODES * 8;
    float* EmW = g_EmB + (size_t)(rd ^ 1) * N_NODES * 8;
    float* EpW = g_EpB + (size_t)(rd ^ 1) * N_NODES * 8;

    float4 u4 = *(const float4*)(EmR + (size_t)n * 8);
    float2 u2 = *(const float2*)(EmR + (size_t)n * 8 + 4);
    float4 w4 = *(const float4*)(EpR + (size_t)n * 8);
    float2 w2 = *(const float2*)(EpR + (size_t)n * 8 + 4);
    float u[6] = {u4.x, u4.y, u4.z, u4.w, u2.x, u2.y};
    float w[6] = {w4.x, w4.y, w4.z, w4.w, w2.x, w2.y};

    float c[6];
#pragma unroll
    for (int i = 0; i < 6; i++) c[i] = __ldg(cw + i);

    float acc[6] = {0.f, 0.f, 0.f, 0.f, 0.f, 0.f};

    int dx = min(g_cX[n], CAP);
    int dy = min(g_cY[n], CAP);

#pragma unroll 2
    for (int i = 0; i < dx; i++) {
        float2 rec = g_LX[(size_t)i * N_NODES + n];
        int b = __float_as_int(rec.x);
        float v = rec.y;
        const float* tb = EpR + (size_t)b * 8;
        float4 o4 = *(const float4*)tb;
        float2 o2 = *(const float2*)(tb + 4);
        acc[0] -= c[0] * u[0] * rcpa(u[0] + v + o4.x);
        acc[1] -= c[1] * u[1] * rcpa(u[1] + v + o4.y);
        acc[2] -= c[2] * u[2] * rcpa(u[2] + v + o4.z);
        acc[3] -= c[3] * u[3] * rcpa(u[3] + v + o4.w);
        acc[4] -= c[4] * u[4] * rcpa(u[4] + v + o2.x);
        acc[5] -= c[5] * u[5] * rcpa(u[5] + v + o2.y);
    }
#pragma unroll 2
    for (int i = 0; i < dy; i++) {
        float2 rec = g_LY[(size_t)i * N_NODES + n];
        int a = __float_as_int(rec.x);
        float v = rec.y;
        const float* ta = EmR + (size_t)a * 8;
        float4 o4 = *(const float4*)ta;
        float2 o2 = *(const float2*)(ta + 4);
        acc[0] += c[0] * w[0] * rcpa(o4.x + v + w[0]);
        acc[1] += c[1] * w[1] * rcpa(o4.y + v + w[1]);
        acc[2] += c[2] * w[2] * rcpa(o4.z + v + w[2]);
        acc[3] += c[3] * w[3] * rcpa(o4.w + v + w[3]);
        acc[4] += c[4] * w[4] * rcpa(o2.x + v + w[4]);
        acc[5] += c[5] * w[5] * rcpa(o2.y + v + w[5]);
    }

    float* zp = &g_z[(size_t)n * 8];
    float4 z4 = *(const float4*)zp;
    float2 z2 = *(const float2*)(zp + 4);
    float zn[6] = {z4.x + acc[0], z4.y + acc[1], z4.z + acc[2],
                   z4.w + acc[3], z2.x + acc[4], z2.y + acc[5]};
    *(float4*)zp       = make_float4(zn[0], zn[1], zn[2], zn[3]);
    *(float2*)(zp + 4) = make_float2(zn[4], zn[5]);

    if (!last) {
        float em[6], ep[6];
#pragma unroll
        for (int k = 0; k < 6; k++) { ep[k] = __expf(zn[k]); em[k] = __expf(-zn[k]); }
        float* e1 = EmW + (size_t)n * 8;
        float* e2 = EpW + (size_t)n * 8;
        *(float4*)e1       = make_float4(em[0], em[1], em[2], em[3]);
        *(float2*)(e1 + 4) = make_float2(em[4], em[5]);
        *(float4*)e2       = make_float4(ep[0], ep[1], ep[2], ep[3]);
        *(float2*)(e2 + 4) = make_float2(ep[4], ep[5]);
    } else {
        float mx = zn[0];
#pragma unroll
        for (int k = 1; k < 6; k++) mx = fmaxf(mx, zn[k]);
        float e[6], s = 0.f;
#pragma unroll
        for (int k = 0; k < 6; k++) { e[k] = __expf(zn[k] - mx); s += e[k]; }
        float inv = rcpa(s);
        float* op = out + (size_t)n * 6;
        *(float2*)op       = make_float2(e[0] * inv, e[1] * inv);
        *(float2*)(op + 2) = make_float2(e[2] * inv, e[3] * inv);
        *(float2*)(op + 4) = make_float2(e[4] * inv, e[5] * inv);
    }
}

// ---------------- launcher ------------------------------------------------
extern "C" void kernel_launch(void* const* d_in, const int* in_sizes, int n_in,
                              void* d_out, int out_size)
{
    const float* F   = (const float*)d_in[0];
    const float* rel = (const float*)d_in[1];
    const int*   sx  = (const int*)d_in[2];
    const int*   sy  = (const int*)d_in[3];
    const float* W1  = (const float*)d_in[4];
    const float* b1  = (const float*)d_in[5];
    const float* W2  = (const float*)d_in[6];
    const float* b2  = (const float*)d_in[7];
    const float* W3  = (const float*)d_in[8];
    const float* b3  = (const float*)d_in[9];
    const float* W4  = (const float*)d_in[10];
    const float* b4  = (const float*)d_in[11];
    const float* cw  = (const float*)d_in[12];
    float* out = (float*)d_out;

    w1split_kernel <<<(128 * NT * 8 * 4 + 255) / 256, 256>>>(W1);     // 0
    zero_kernel    <<<(N_NODES + 255) / 256, 256>>>();                // 1
    prep_kernel    <<<(M_EDGES + 255) / 256, 256>>>(rel, sx, sy);     // 2
    gemm1_mma_kernel<<<(N_NODES + 127) / 128, 128>>>(F, b1);          // 3 <- ncu slot
    mlp_tail_kernel<<<(N_NODES + 127) / 128, 128>>>(W2, b2, W3, b3, W4, b4); // 4

    int grid = (N_NODES + 255) / 256;
    layer_kernel<<<grid, 256>>>(cw + 0,  0, 0, out);                  // 5
    layer_kernel<<<grid, 256>>>(cw + 6,  1, 0, out);                  // 6
    layer_kernel<<<grid, 256>>>(cw + 12, 0, 1, out);                  // 7
}

// round 16
// speedup vs baseline: 1.0378x; 1.0378x over previous
#include <cuda_runtime.h>
#include <cuda_bf16.h>

#define N_NODES 100000
#define D_IN    2048
#define H_DIM   50
#define C_CLS   6
#define M_EDGES 3200000
#define L_LAYERS 3
#define CAP     128          // per-node per-direction edge capacity (mean deg 32)
#define KC      64           // gemm1 K-chunk
#define NT      7            // n-tiles (7*8 = 56 >= 50)

// ---------------- scratch (device globals; no allocation allowed) ----------
__device__ __align__(16) float2 g_LX[CAP * N_NODES];   // slot-major: [slot][node] = {other, v}
__device__ __align__(16) float2 g_LY[CAP * N_NODES];
__device__ int g_cX[N_NODES];
__device__ int g_cY[N_NODES];
__device__ __align__(16) float g_x1[N_NODES * H_DIM];  // layer-1 activations
__device__ __align__(16) float g_z [N_NODES * 8];      // z padded to 8 floats/row
__device__ __align__(16) float g_EmB[2 * N_NODES * 8]; // e^{-z}, double-buffered
__device__ __align__(16) float g_EpB[2 * N_NODES * 8]; // e^{+z}, double-buffered
// W1 in pre-permuted mma-fragment layout: [s=128][n=56][tg=4] x uint4
// uint4 = {bh(k0,k0+1), bh(k0+8,k0+9), bl(k0,k0+1), bl(k0+8,k0+9)}, k0=16s+2tg
__device__ __align__(16) uint4 g_W1p[128 * NT * 8 * 4];

typedef unsigned long long ull;

__device__ __forceinline__ ull pack2(float x, float y) {
    ull r; asm("mov.b64 %0, {%1, %2};" : "=l"(r) : "f"(x), "f"(y)); return r;
}
__device__ __forceinline__ void unpack2(ull v, float& x, float& y) {
    asm("mov.b64 {%0, %1}, %2;" : "=f"(x), "=f"(y) : "l"(v));
}
__device__ __forceinline__ ull ffma2(ull a, ull b, ull c) {
    ull d; asm("fma.rn.f32x2 %0, %1, %2, %3;" : "=l"(d) : "l"(a), "l"(b), "l"(c)); return d;
}
__device__ __forceinline__ float rcpa(float x) {
    float r; asm("rcp.approx.f32 %0, %1;" : "=f"(r) : "f"(x)); return r;
}
// pack two f32 -> bf16x2 (x1 -> high half, x0 -> low half)
__device__ __forceinline__ unsigned int cvt_bf16x2(float x1, float x0) {
    unsigned int r;
    asm("cvt.rn.bf16x2.f32 %0, %1, %2;" : "=r"(r) : "f"(x1), "f"(x0));
    return r;
}
// split float2 into hi bf16x2 and residual-lo bf16x2
__device__ __forceinline__ void split2(float2 x, unsigned int& h, unsigned int& l) {
    h = cvt_bf16x2(x.y, x.x);
    float l0 = x.x - __uint_as_float(h << 16);
    float l1 = x.y - __uint_as_float(h & 0xffff0000u);
    l = cvt_bf16x2(l1, l0);
}
__device__ __forceinline__ void mma16816(float* d,
    unsigned int a0, unsigned int a1, unsigned int a2, unsigned int a3,
    unsigned int b0, unsigned int b1)
{
    asm volatile(
        "mma.sync.aligned.m16n8k16.row.col.f32.bf16.bf16.f32 "
        "{%0,%1,%2,%3}, {%4,%5,%6,%7}, {%8,%9}, {%0,%1,%2,%3};"
        : "+f"(d[0]), "+f"(d[1]), "+f"(d[2]), "+f"(d[3])
        : "r"(a0), "r"(a1), "r"(a2), "r"(a3), "r"(b0), "r"(b1));
}
__device__ __forceinline__ void cp_async16(unsigned int smem_dst, const void* gsrc) {
    asm volatile("cp.async.cg.shared.global [%0], [%1], 16;" :: "r"(smem_dst), "l"(gsrc));
}

// ---------------- K-2: W1 -> permuted bf16 hi/lo fragment layout ----------
// linear idx = s*(NT*8*4) + n*4 + tg,  n in [0,56), k0 = 16s + 2tg
__global__ void w1split_kernel(const float* __restrict__ W1) {
    int idx = blockIdx.x * 256 + threadIdx.x;
    if (idx >= 128 * NT * 8 * 4) return;
    int tg = idx & 3;
    int n  = (idx >> 2) % (NT * 8);
    int s  = idx / (NT * 8 * 4);
    int k0 = s * 16 + 2 * tg;
    unsigned short h[4], l[4];
#pragma unroll
    for (int j = 0; j < 4; j++) {
        int k = k0 + (j >> 1) * 8 + (j & 1);    // k0, k0+1, k0+8, k0+9
        float w = (n < H_DIM) ? W1[k * H_DIM + n] : 0.f;
        __nv_bfloat16 hb = __float2bfloat16(w);
        float hf = __bfloat162float(hb);
        __nv_bfloat16 lb = __float2bfloat16(w - hf);
        h[j] = __bfloat16_as_ushort(hb);
        l[j] = __bfloat16_as_ushort(lb);
    }
    uint4 v;
    v.x = (unsigned int)h[0] | ((unsigned int)h[1] << 16);
    v.y = (unsigned int)h[2] | ((unsigned int)h[3] << 16);
    v.z = (unsigned int)l[0] | ((unsigned int)l[1] << 16);
    v.w = (unsigned int)l[2] | ((unsigned int)l[3] << 16);
    g_W1p[idx] = v;
}

// ---------------- K-1: zero the CSR counters ------------------------------
__global__ void zero_kernel() {
    int n = blockIdx.x * 256 + threadIdx.x;
    if (n < N_NODES) { g_cX[n] = 0; g_cY[n] = 0; }
}

// ---------------- K0: bucket edges into pull lists ------------------------
__global__ void prep_kernel(const float* __restrict__ rel,
                            const int* __restrict__ sx,
                            const int* __restrict__ sy) {
    int m = blockIdx.x * 256 + threadIdx.x;
    if (m >= M_EDGES) return;
    int a = sx[m], b = sy[m];
    float v = __expf(-rel[m]);
    int ix = atomicAdd(&g_cX[a], 1);
    if (ix < CAP) g_LX[(size_t)ix * N_NODES + a] = make_float2(__int_as_float(b), v);
    int iy = atomicAdd(&g_cY[b], 1);
    if (iy < CAP) g_LY[(size_t)iy * N_NODES + b] = make_float2(__int_as_float(a), v);
}

// ---------------- K1: x1 = relu(F @ W1 + b1), bf16-split MMA v5 ----------
// = round-14 v3 structure (rA/rAn A-pipeline), NT=7 work reduction only.
// 128 thr / 4 warps / m32 per warp / 128 rows per CTA.
// A: direct LDG in frag layout, software-pipelined one s-step ahead.
// B: pre-permuted frag layout; ONE LDS.128 per (nt,s) gives the whole
// b-frag. cp.async double-buffered 14KB chunks.
__global__ __launch_bounds__(128, 4) void gemm1_mma_kernel(
    const float* __restrict__ F, const float* __restrict__ b1)
{
    __shared__ __align__(16) uint4 sB[2][4 * NT * 8 * 4];   // 14KB per buf

    int tid  = threadIdx.x;
    int n0   = blockIdx.x * 128;
    int lane = tid & 31, wid = tid >> 5;
    int g = lane >> 2, tg = lane & 3;

    int r0 = n0 + wid * 32 + g;
    bool ok[4] = { r0 < N_NODES, r0 + 8 < N_NODES, r0 + 16 < N_NODES, r0 + 24 < N_NODES };
    const float* Fr[4] = {
        F + (size_t)(r0     ) * D_IN, F + (size_t)(r0 + 8 ) * D_IN,
        F + (size_t)(r0 + 16) * D_IN, F + (size_t)(r0 + 24) * D_IN };

    // stage B chunk 0 (896 uint4 = 7 per thread)
#pragma unroll
    for (int i = 0; i < 7; i++) {
        int x = i * 128 + tid;
        cp_async16((unsigned int)__cvta_generic_to_shared(&sB[0][x]), g_W1p + x);
    }
    asm volatile("cp.async.commit_group;");

    // A fragment registers: rA[t*4+j] = {t,j} frag; prefetch s=0
    float2 rA[8], rAn[8];
    float2 zf = make_float2(0.f, 0.f);
#pragma unroll
    for (int t = 0; t < 2; t++)
#pragma unroll
        for (int j = 0; j < 2; j++) {
            rA[t * 4 + j]     = ok[t * 2 + j] ? *(const float2*)(Fr[t * 2 + j] + 2 * tg)     : zf;
            rA[t * 4 + j + 2] = ok[t * 2 + j] ? *(const float2*)(Fr[t * 2 + j] + 2 * tg + 8) : zf;
        }

    float d[2][NT][4];
#pragma unroll
    for (int t = 0; t < 2; t++)
#pragma unroll
        for (int nt = 0; nt < NT; nt++)
#pragma unroll
            for (int j = 0; j < 4; j++) d[t][nt][j] = 0.f;

    asm volatile("cp.async.wait_group 0;");
    __syncthreads();

    int p = 0;
    for (int kc = 0; kc < D_IN; kc += KC) {
        int kn = kc + KC;
        if (kn < D_IN) {     // prefetch next B chunk into buf p^1
            const uint4* src = g_W1p + (kn >> 4) * (NT * 8 * 4);
#pragma unroll
            for (int i = 0; i < 7; i++) {
                int x = i * 128 + tid;
                cp_async16((unsigned int)__cvta_generic_to_shared(&sB[p ^ 1][x]), src + x);
            }
            asm volatile("cp.async.commit_group;");
        }

        const uint4* bp = sB[p];
#pragma unroll
        for (int s = 0; s < 4; s++) {
            // prefetch A for next s-step (chunk-crossing at s==3)
            int cnext = (s < 3) ? (kc + (s + 1) * 16 + 2 * tg)
                                : ((kn < D_IN) ? (kn + 2 * tg) : (kc + 2 * tg));
#pragma unroll
            for (int t = 0; t < 2; t++)
#pragma unroll
                for (int j = 0; j < 2; j++) {
                    rAn[t * 4 + j]     = ok[t * 2 + j] ? *(const float2*)(Fr[t * 2 + j] + cnext)     : zf;
                    rAn[t * 4 + j + 2] = ok[t * 2 + j] ? *(const float2*)(Fr[t * 2 + j] + cnext + 8) : zf;
                }

            // split current A to bf16 hi/lo
            unsigned int ah[2][4], al[2][4];
#pragma unroll
            for (int t = 0; t < 2; t++)
#pragma unroll
                for (int j = 0; j < 4; j++)
                    split2(rA[t * 4 + j], ah[t][j], al[t][j]);

#pragma unroll
            for (int nt = 0; nt < NT; nt++) {
                uint4 bb = bp[s * (NT * 8 * 4) + (nt * 8 + g) * 4 + tg];   // LDS.128, conflict-free
#pragma unroll
                for (int t = 0; t < 2; t++) {
                    mma16816(d[t][nt], ah[t][0], ah[t][1], ah[t][2], ah[t][3], bb.x, bb.y);
                    mma16816(d[t][nt], ah[t][0], ah[t][1], ah[t][2], ah[t][3], bb.z, bb.w);
                    mma16816(d[t][nt], al[t][0], al[t][1], al[t][2], al[t][3], bb.x, bb.y);
                }
            }
#pragma unroll
            for (int i = 0; i < 8; i++) rA[i] = rAn[i];
        }

        if (kn < D_IN) { asm volatile("cp.async.wait_group 0;"); }
        __syncthreads();
        p ^= 1;
    }

    // ---- epilogue: bias + relu -> g_x1 [node][50] ----
#pragma unroll
    for (int t = 0; t < 2; t++) {
        int row0 = n0 + wid * 32 + t * 16 + g;
#pragma unroll
        for (int nt = 0; nt < NT; nt++) {
            int col = nt * 8 + 2 * tg;
            if (col < H_DIM) {        // 50 even: float2 pairs never straddle
                float bb0 = __ldg(&b1[col]), bb1 = __ldg(&b1[col + 1]);
                if (row0 < N_NODES) {
                    float2 o = make_float2(fmaxf(d[t][nt][0] + bb0, 0.f),
                                           fmaxf(d[t][nt][1] + bb1, 0.f));
                    *(float2*)&g_x1[(size_t)row0 * H_DIM + col] = o;
                }
                int row1 = row0 + 8;
                if (row1 < N_NODES) {
                    float2 o = make_float2(fmaxf(d[t][nt][2] + bb0, 0.f),
                                           fmaxf(d[t][nt][3] + bb1, 0.f));
                    *(float2*)&g_x1[(size_t)row1 * H_DIM + col] = o;
                }
            }
        }
    }
}

// ---------------- K2: fused layers 2..4 -> z + initial exp tables ---------
// Weights in padded stride-52 rows: 12 LDS.128 + 1 LDS.64 per k (was 25 LDS.64).
__global__ __launch_bounds__(128) void mlp_tail_kernel(
    const float* __restrict__ W2, const float* __restrict__ b2,
    const float* __restrict__ W3, const float* __restrict__ b3,
    const float* __restrict__ W4, const float* __restrict__ b4)
{
    __shared__ __align__(16) float sW2[50 * 52];
    __shared__ __align__(16) float sW3[50 * 52];
    __shared__ __align__(16) float sW4[304];
    __shared__ float sB2[56], sB3[56], sB4[8];

    int tid = threadIdx.x;
    for (int i = tid; i < 50 * 52; i += 128) {
        int r = i / 52, c = i - r * 52;
        float v2 = (c < 50) ? W2[r * 50 + c] : 0.f;
        float v3 = (c < 50) ? W3[r * 50 + c] : 0.f;
        sW2[i] = v2; sW3[i] = v3;
    }
    for (int i = tid; i < 300;  i += 128) sW4[i] = W4[i];
    if (tid < 50) { sB2[tid] = b2[tid]; sB3[tid] = b3[tid]; }
    if (tid < 6)  sB4[tid] = b4[tid];
    __syncthreads();

    int node = blockIdx.x * 128 + tid;
    if (node >= N_NODES) return;

    float xa[50];
    const float* xin = &g_x1[(size_t)node * H_DIM];
#pragma unroll
    for (int j = 0; j < 25; j++) {
        float2 v = *(const float2*)(xin + 2 * j);
        xa[2 * j] = v.x; xa[2 * j + 1] = v.y;
    }

    // layer 2
    {
        ull acc[25];
#pragma unroll
        for (int j = 0; j < 25; j++) acc[j] = 0ull;
#pragma unroll
        for (int k = 0; k < 50; k++) {
            ull f2 = pack2(xa[k], xa[k]);
            const ull* wr = (const ull*)&sW2[k * 52];
#pragma unroll
            for (int j = 0; j < 12; j++) {
                ulonglong2 w2 = *(const ulonglong2*)(wr + 2 * j);   // LDS.128
                acc[2 * j]     = ffma2(f2, w2.x, acc[2 * j]);
                acc[2 * j + 1] = ffma2(f2, w2.y, acc[2 * j + 1]);
            }
            acc[24] = ffma2(f2, wr[24], acc[24]);                   // LDS.64
        }
#pragma unroll
        for (int j = 0; j < 25; j++) {
            float a, b; unpack2(acc[j], a, b);
            xa[2 * j]     = fmaxf(a + sB2[2 * j],     0.f);
            xa[2 * j + 1] = fmaxf(b + sB2[2 * j + 1], 0.f);
        }
    }
    // layer 3
    {
        ull acc[25];
#pragma unroll
        for (int j = 0; j < 25; j++) acc[j] = 0ull;
#pragma unroll
        for (int k = 0; k < 50; k++) {
            ull f2 = pack2(xa[k], xa[k]);
            const ull* wr = (const ull*)&sW3[k * 52];
#pragma unroll
            for (int j = 0; j < 12; j++) {
                ulonglong2 w2 = *(const ulonglong2*)(wr + 2 * j);   // LDS.128
                acc[2 * j]     = ffma2(f2, w2.x, acc[2 * j]);
                acc[2 * j + 1] = ffma2(f2, w2.y, acc[2 * j + 1]);
            }
            acc[24] = ffma2(f2, wr[24], acc[24]);                   // LDS.64
        }
#pragma unroll
        for (int j = 0; j < 25; j++) {
            float a, b; unpack2(acc[j], a, b);
            xa[2 * j]     = fmaxf(a + sB3[2 * j],     0.f);
            xa[2 * j + 1] = fmaxf(b + sB3[2 * j + 1], 0.f);
        }
    }
    // layer 4 -> z, plus exp tables for KENN layer 0 (buffer 0)
    {
        ull acc[3] = {0ull, 0ull, 0ull};
#pragma unroll
        for (int k = 0; k < 50; k++) {
            ull f2 = pack2(xa[k], xa[k]);
            const float* wr = &sW4[k * 6];
#pragma unroll
            for (int j = 0; j < 3; j++)
                acc[j] = ffma2(f2, *(const ull*)(wr + 2 * j), acc[j]);
        }
        float zr[6];
#pragma unroll
        for (int j = 0; j < 3; j++) {
            float a, b; unpack2(acc[j], a, b);
            zr[2 * j]     = a + sB4[2 * j];
            zr[2 * j + 1] = b + sB4[2 * j + 1];
        }
        float* zp = &g_z[(size_t)node * 8];
        *(float4*)zp       = make_float4(zr[0], zr[1], zr[2], zr[3]);
        *(float2*)(zp + 4) = make_float2(zr[4], zr[5]);

        float em[6], ep[6];
#pragma unroll
        for (int c = 0; c < 6; c++) { ep[c] = __expf(zr[c]); em[c] = __expf(-zr[c]); }
        float* e1 = &g_EmB[(size_t)node * 8];
        float* e2 = &g_EpB[(size_t)node * 8];
        *(float4*)e1       = make_float4(em[0], em[1], em[2], em[3]);
        *(float2*)(e1 + 4) = make_float2(em[4], em[5]);
        *(float4*)e2       = make_float4(ep[0], ep[1], ep[2], ep[3]);
        *(float2*)(e2 + 4) = make_float2(ep[4], ep[5]);
    }
}

// ---------------- K3: KENN layer, pull-based (no atomics) -----------------
__global__ __launch_bounds__(256) void layer_kernel(
    const float* __restrict__ cw, int rd, int last, float* __restrict__ out)
{
    int n = blockIdx.x * 256 + threadIdx.x;
    if (n >= N_NODES) return;

    const float* EmR = g_EmB + (size_t)rd * N_NODES * 8;
    const float* EpR = g_EpB + (size_t)rd * N_NODES * 8;
    float* EmW = g_EmB + (size_t)(rd ^ 1) * N_NODES * 8;
    float* EpW = g_EpB + (size_t)(rd ^ 1) * N_NODES * 8;

    float4 u4 = *(const float4*)(EmR + (size_t)n * 8);
    float2 u2 = *(const float2*)(EmR + (size_t)n * 8 + 4);
    float4 w4 = *(const float4*)(EpR + (size_t)n * 8);
    float2 w2 = *(const float2*)(EpR + (size_t)n * 8 + 4);
    float u[6] = {u4.x, u4.y, u4.z, u4.w, u2.x, u2.y};
    float w[6] = {w4.x, w4.y, w4.z, w4.w, w2.x, w2.y};

    float c[6];
#pragma unroll
    for (int i = 0; i < 6; i++) c[i] = __ldg(cw + i);

    float acc[6] = {0.f, 0.f, 0.f, 0.f, 0.f, 0.f};

    int dx = min(g_cX[n], CAP);
    int dy = min(g_cY[n], CAP);

#pragma unroll 2
    for (int i = 0; i < dx; i++) {
        float2 rec = g_LX[(size_t)i * N_NODES + n];
        int b = __float_as_int(rec.x);
        float v = rec.y;
        const float* tb = EpR + (size_t)b * 8;
        float4 o4 = *(const float4*)tb;
        float2 o2 = *(const float2*)(tb + 4);
        acc[0] -= c[0] * u[0] * rcpa(u[0] + v + o4.x);
        acc[1] -= c[1] * u[1] * rcpa(u[1] + v + o4.y);
        acc[2] -= c[2] * u[2] * rcpa(u[2] + v + o4.z);
        acc[3] -= c[3] * u[3] * rcpa(u[3] + v + o4.w);
        acc[4] -= c[4] * u[4] * rcpa(u[4] + v + o2.x);
        acc[5] -= c[5] * u[5] * rcpa(u[5] + v + o2.y);
    }
#pragma unroll 2
    for (int i = 0; i < dy; i++) {
        float2 rec = g_LY[(size_t)i * N_NODES + n];
        int a = __float_as_int(rec.x);
        float v = rec.y;
        const float* ta = EmR + (size_t)a * 8;
        float4 o4 = *(const float4*)ta;
        float2 o2 = *(const float2*)(ta + 4);
        acc[0] += c[0] * w[0] * rcpa(o4.x + v + w[0]);
        acc[1] += c[1] * w[1] * rcpa(o4.y + v + w[1]);
        acc[2] += c[2] * w[2] * rcpa(o4.z + v + w[2]);
        acc[3] += c[3] * w[3] * rcpa(o4.w + v + w[3]);
        acc[4] += c[4] * w[4] * rcpa(o2.x + v + w[4]);
        acc[5] += c[5] * w[5] * rcpa(o2.y + v + w[5]);
    }

    float* zp = &g_z[(size_t)n * 8];
    float4 z4 = *(const float4*)zp;
    float2 z2 = *(const float2*)(zp + 4);
    float zn[6] = {z4.x + acc[0], z4.y + acc[1], z4.z + acc[2],
                   z4.w + acc[3], z2.x + acc[4], z2.y + acc[5]};
    *(float4*)zp       = make_float4(zn[0], zn[1], zn[2], zn[3]);
    *(float2*)(zp + 4) = make_float2(zn[4], zn[5]);

    if (!last) {
        float em[6], ep[6];
#pragma unroll
        for (int k = 0; k < 6; k++) { ep[k] = __expf(zn[k]); em[k] = __expf(-zn[k]); }
        float* e1 = EmW + (size_t)n * 8;
        float* e2 = EpW + (size_t)n * 8;
        *(float4*)e1       = make_float4(em[0], em[1], em[2], em[3]);
        *(float2*)(e1 + 4) = make_float2(em[4], em[5]);
        *(float4*)e2       = make_float4(ep[0], ep[1], ep[2], ep[3]);
        *(float2*)(e2 + 4) = make_float2(ep[4], ep[5]);
    } else {
        float mx = zn[0];
#pragma unroll
        for (int k = 1; k < 6; k++) mx = fmaxf(mx, zn[k]);
        float e[6], s = 0.f;
#pragma unroll
        for (int k = 0; k < 6; k++) { e[k] = __expf(zn[k] - mx); s += e[k]; }
        float inv = rcpa(s);
        float* op = out + (size_t)n * 6;
        *(float2*)op       = make_float2(e[0] * inv, e[1] * inv);
        *(float2*)(op + 2) = make_float2(e[2] * inv, e[3] * inv);
        *(float2*)(op + 4) = make_float2(e[4] * inv, e[5] * inv);
    }
}

// ---------------- launcher ------------------------------------------------
extern "C" void kernel_launch(void* const* d_in, const int* in_sizes, int n_in,
                              void* d_out, int out_size)
{
    const float* F   = (const float*)d_in[0];
    const float* rel = (const float*)d_in[1];
    const int*   sx  = (const int*)d_in[2];
    const int*   sy  = (const int*)d_in[3];
    const float* W1  = (const float*)d_in[4];
    const float* b1  = (const float*)d_in[5];
    const float* W2  = (const float*)d_in[6];
    const float* b2  = (const float*)d_in[7];
    const float* W3  = (const float*)d_in[8];
    const float* b3  = (const float*)d_in[9];
    const float* W4  = (const float*)d_in[10];
    const float* b4  = (const float*)d_in[11];
    const float* cw  = (const float*)d_in[12];
    float* out = (float*)d_out;

    w1split_kernel <<<(128 * NT * 8 * 4 + 255) / 256, 256>>>(W1);     // 0
    zero_kernel    <<<(N_NODES + 255) / 256, 256>>>();                // 1
    prep_kernel    <<<(M_EDGES + 255) / 256, 256>>>(rel, sx, sy);     // 2
    gemm1_mma_kernel<<<(N_NODES + 127) / 128, 128>>>(F, b1);          // 3 <- ncu slot
    mlp_tail_kernel<<<(N_NODES + 127) / 128, 128>>>(W2, b2, W3, b3, W4, b4); // 4

    int grid = (N_NODES + 255) / 256;
    layer_kernel<<<grid, 256>>>(cw + 0,  0, 0, out);                  // 5
    layer_kernel<<<grid, 256>>>(cw + 6,  1, 0, out);                  // 6
    layer_kernel<<<grid, 256>>>(cw + 12, 0, 1, out);                  // 7
}

// round 17
// speedup vs baseline: 1.0450x; 1.0070x over previous
#include <cuda_runtime.h>
#include <cuda_bf16.h>

#define N_NODES 100000
#define D_IN    2048
#define H_DIM   50
#define C_CLS   6
#define M_EDGES 3200000
#define L_LAYERS 3
#define CAP     128          // per-node per-direction edge capacity (mean deg 32)
#define KC      128          // gemm1 K-chunk (8 s-steps)
#define NT      7            // n-tiles (7*8 = 56 >= 50)

// ---------------- scratch (device globals; no allocation allowed) ----------
__device__ __align__(16) float2 g_LX[CAP * N_NODES];   // slot-major: [slot][node] = {other, v}
__device__ __align__(16) float2 g_LY[CAP * N_NODES];
__device__ int g_cX[N_NODES];
__device__ int g_cY[N_NODES];
__device__ __align__(16) float g_x1[N_NODES * H_DIM];  // layer-1 activations
__device__ __align__(16) float g_z [N_NODES * 8];      // z padded to 8 floats/row
__device__ __align__(16) float g_EmB[2 * N_NODES * 8]; // e^{-z}, double-buffered
__device__ __align__(16) float g_EpB[2 * N_NODES * 8]; // e^{+z}, double-buffered
// W1 in pre-permuted mma-fragment layout: [s=128][n=56][tg=4] x uint4
// uint4 = {bh(k0,k0+1), bh(k0+8,k0+9), bl(k0,k0+1), bl(k0+8,k0+9)}, k0=16s+2tg
__device__ __align__(16) uint4 g_W1p[128 * NT * 8 * 4];

typedef unsigned long long ull;

__device__ __forceinline__ ull pack2(float x, float y) {
    ull r; asm("mov.b64 %0, {%1, %2};" : "=l"(r) : "f"(x), "f"(y)); return r;
}
__device__ __forceinline__ void unpack2(ull v, float& x, float& y) {
    asm("mov.b64 {%0, %1}, %2;" : "=f"(x), "=f"(y) : "l"(v));
}
__device__ __forceinline__ ull ffma2(ull a, ull b, ull c) {
    ull d; asm("fma.rn.f32x2 %0, %1, %2, %3;" : "=l"(d) : "l"(a), "l"(b), "l"(c)); return d;
}
__device__ __forceinline__ float rcpa(float x) {
    float r; asm("rcp.approx.f32 %0, %1;" : "=f"(r) : "f"(x)); return r;
}
// pack two f32 -> bf16x2 (x1 -> high half, x0 -> low half)
__device__ __forceinline__ unsigned int cvt_bf16x2(float x1, float x0) {
    unsigned int r;
    asm("cvt.rn.bf16x2.f32 %0, %1, %2;" : "=r"(r) : "f"(x1), "f"(x0));
    return r;
}
// split float2 into hi bf16x2 and residual-lo bf16x2
__device__ __forceinline__ void split2(float2 x, unsigned int& h, unsigned int& l) {
    h = cvt_bf16x2(x.y, x.x);
    float l0 = x.x - __uint_as_float(h << 16);
    float l1 = x.y - __uint_as_float(h & 0xffff0000u);
    l = cvt_bf16x2(l1, l0);
}
__device__ __forceinline__ void mma16816(float* d,
    unsigned int a0, unsigned int a1, unsigned int a2, unsigned int a3,
    unsigned int b0, unsigned int b1)
{
    asm volatile(
        "mma.sync.aligned.m16n8k16.row.col.f32.bf16.bf16.f32 "
        "{%0,%1,%2,%3}, {%4,%5,%6,%7}, {%8,%9}, {%0,%1,%2,%3};"
        : "+f"(d[0]), "+f"(d[1]), "+f"(d[2]), "+f"(d[3])
        : "r"(a0), "r"(a1), "r"(a2), "r"(a3), "r"(b0), "r"(b1));
}
__device__ __forceinline__ void cp_async16(unsigned int smem_dst, const void* gsrc) {
    asm volatile("cp.async.cg.shared.global [%0], [%1], 16;" :: "r"(smem_dst), "l"(gsrc));
}

// ---------------- K-2: W1 -> permuted bf16 hi/lo fragment layout ----------
// linear idx = s*(NT*8*4) + n*4 + tg,  n in [0,56), k0 = 16s + 2tg
__global__ void w1split_kernel(const float* __restrict__ W1) {
    int idx = blockIdx.x * 256 + threadIdx.x;
    if (idx >= 128 * NT * 8 * 4) return;
    int tg = idx & 3;
    int n  = (idx >> 2) % (NT * 8);
    int s  = idx / (NT * 8 * 4);
    int k0 = s * 16 + 2 * tg;
    unsigned short h[4], l[4];
#pragma unroll
    for (int j = 0; j < 4; j++) {
        int k = k0 + (j >> 1) * 8 + (j & 1);    // k0, k0+1, k0+8, k0+9
        float w = (n < H_DIM) ? W1[k * H_DIM + n] : 0.f;
        __nv_bfloat16 hb = __float2bfloat16(w);
        float hf = __bfloat162float(hb);
        __nv_bfloat16 lb = __float2bfloat16(w - hf);
        h[j] = __bfloat16_as_ushort(hb);
        l[j] = __bfloat16_as_ushort(lb);
    }
    uint4 v;
    v.x = (unsigned int)h[0] | ((unsigned int)h[1] << 16);
    v.y = (unsigned int)h[2] | ((unsigned int)h[3] << 16);
    v.z = (unsigned int)l[0] | ((unsigned int)l[1] << 16);
    v.w = (unsigned int)l[2] | ((unsigned int)l[3] << 16);
    g_W1p[idx] = v;
}

// ---------------- K-1: zero the CSR counters ------------------------------
__global__ void zero_kernel() {
    int n = blockIdx.x * 256 + threadIdx.x;
    if (n < N_NODES) { g_cX[n] = 0; g_cY[n] = 0; }
}

// ---------------- K0: bucket edges into pull lists ------------------------
__global__ void prep_kernel(const float* __restrict__ rel,
                            const int* __restrict__ sx,
                            const int* __restrict__ sy) {
    int m = blockIdx.x * 256 + threadIdx.x;
    if (m >= M_EDGES) return;
    int a = sx[m], b = sy[m];
    float v = __expf(-rel[m]);
    int ix = atomicAdd(&g_cX[a], 1);
    if (ix < CAP) g_LX[(size_t)ix * N_NODES + a] = make_float2(__int_as_float(b), v);
    int iy = atomicAdd(&g_cY[b], 1);
    if (iy < CAP) g_LY[(size_t)iy * N_NODES + b] = make_float2(__int_as_float(a), v);
}

// ---------------- K1: x1 = relu(F @ W1 + b1), bf16-split MMA v6 ----------
// 256 thr / 8 warps / m32 per warp / 256 rows per CTA -> 2 CTAs/SM
// (32K regs/CTA), 16 warps/SM. KC=128: 16 chunks, half the barriers,
// double the cp.async overlap window (2 x 28KB smem).
// A: direct LDG in frag layout, software-pipelined one s-step ahead.
// B: pre-permuted frag layout; ONE LDS.128 per (nt,s) gives the whole
// b-frag (conflict-free).
__global__ __launch_bounds__(256, 2) void gemm1_mma_kernel(
    const float* __restrict__ F, const float* __restrict__ b1)
{
    __shared__ __align__(16) uint4 sB[2][8 * NT * 8 * 4];   // 28KB per buf

    const int CHUNK_U4 = 8 * NT * 8 * 4;    // 1792 uint4 per chunk
    int tid  = threadIdx.x;
    int n0   = blockIdx.x * 256;
    int lane = tid & 31, wid = tid >> 5;    // wid 0..7
    int g = lane >> 2, tg = lane & 3;

    int r0 = n0 + wid * 32 + g;
    bool ok[4] = { r0 < N_NODES, r0 + 8 < N_NODES, r0 + 16 < N_NODES, r0 + 24 < N_NODES };
    const float* Fr[4] = {
        F + (size_t)(r0     ) * D_IN, F + (size_t)(r0 + 8 ) * D_IN,
        F + (size_t)(r0 + 16) * D_IN, F + (size_t)(r0 + 24) * D_IN };

    // stage B chunk 0 (1792 uint4 = 7 per thread)
#pragma unroll
    for (int i = 0; i < 7; i++) {
        int x = i * 256 + tid;
        cp_async16((unsigned int)__cvta_generic_to_shared(&sB[0][x]), g_W1p + x);
    }
    asm volatile("cp.async.commit_group;");

    // A fragment registers: rA[t*4+j] = {t,j} frag; prefetch s=0
    float2 rA[8], rAn[8];
    float2 zf = make_float2(0.f, 0.f);
#pragma unroll
    for (int t = 0; t < 2; t++)
#pragma unroll
        for (int j = 0; j < 2; j++) {
            rA[t * 4 + j]     = ok[t * 2 + j] ? *(const float2*)(Fr[t * 2 + j] + 2 * tg)     : zf;
            rA[t * 4 + j + 2] = ok[t * 2 + j] ? *(const float2*)(Fr[t * 2 + j] + 2 * tg + 8) : zf;
        }

    float d[2][NT][4];
#pragma unroll
    for (int t = 0; t < 2; t++)
#pragma unroll
        for (int nt = 0; nt < NT; nt++)
#pragma unroll
            for (int j = 0; j < 4; j++) d[t][nt][j] = 0.f;

    asm volatile("cp.async.wait_group 0;");
    __syncthreads();

    int p = 0;
    for (int kc = 0; kc < D_IN; kc += KC) {
        int kn = kc + KC;
        if (kn < D_IN) {     // prefetch next B chunk into buf p^1
            const uint4* src = g_W1p + (kn >> 4) * (NT * 8 * 4);
#pragma unroll
            for (int i = 0; i < 7; i++) {
                int x = i * 256 + tid;
                cp_async16((unsigned int)__cvta_generic_to_shared(&sB[p ^ 1][x]), src + x);
            }
            asm volatile("cp.async.commit_group;");
        }

        const uint4* bp = sB[p];
#pragma unroll
        for (int s = 0; s < 8; s++) {
            // prefetch A for next s-step (chunk-crossing at s==7)
            int cnext = (s < 7) ? (kc + (s + 1) * 16 + 2 * tg)
                                : ((kn < D_IN) ? (kn + 2 * tg) : (kc + 2 * tg));
#pragma unroll
            for (int t = 0; t < 2; t++)
#pragma unroll
                for (int j = 0; j < 2; j++) {
                    rAn[t * 4 + j]     = ok[t * 2 + j] ? *(const float2*)(Fr[t * 2 + j] + cnext)     : zf;
                    rAn[t * 4 + j + 2] = ok[t * 2 + j] ? *(const float2*)(Fr[t * 2 + j] + cnext + 8) : zf;
                }

            // split current A to bf16 hi/lo
            unsigned int ah[2][4], al[2][4];
#pragma unroll
            for (int t = 0; t < 2; t++)
#pragma unroll
                for (int j = 0; j < 4; j++)
                    split2(rA[t * 4 + j], ah[t][j], al[t][j]);

#pragma unroll
            for (int nt = 0; nt < NT; nt++) {
                uint4 bb = bp[s * (NT * 8 * 4) + (nt * 8 + g) * 4 + tg];   // LDS.128, conflict-free
#pragma unroll
                for (int t = 0; t < 2; t++) {
                    mma16816(d[t][nt], ah[t][0], ah[t][1], ah[t][2], ah[t][3], bb.x, bb.y);
                    mma16816(d[t][nt], ah[t][0], ah[t][1], ah[t][2], ah[t][3], bb.z, bb.w);
                    mma16816(d[t][nt], al[t][0], al[t][1], al[t][2], al[t][3], bb.x, bb.y);
                }
            }
#pragma unroll
            for (int i = 0; i < 8; i++) rA[i] = rAn[i];
        }

        if (kn < D_IN) { asm volatile("cp.async.wait_group 0;"); }
        __syncthreads();
        p ^= 1;
    }

    // ---- epilogue: bias + relu -> g_x1 [node][50] ----
#pragma unroll
    for (int t = 0; t < 2; t++) {
        int row0 = n0 + wid * 32 + t * 16 + g;
#pragma unroll
        for (int nt = 0; nt < NT; nt++) {
            int col = nt * 8 + 2 * tg;
            if (col < H_DIM) {        // 50 even: float2 pairs never straddle
                float bb0 = __ldg(&b1[col]), bb1 = __ldg(&b1[col + 1]);
                if (row0 < N_NODES) {
                    float2 o = make_float2(fmaxf(d[t][nt][0] + bb0, 0.f),
                                           fmaxf(d[t][nt][1] + bb1, 0.f));
                    *(float2*)&g_x1[(size_t)row0 * H_DIM + col] = o;
                }
                int row1 = row0 + 8;
                if (row1 < N_NODES) {
                    float2 o = make_float2(fmaxf(d[t][nt][2] + bb0, 0.f),
                                           fmaxf(d[t][nt][3] + bb1, 0.f));
                    *(float2*)&g_x1[(size_t)row1 * H_DIM + col] = o;
                }
            }
        }
    }
}

// ---------------- K2: fused layers 2..4 -> z + initial exp tables ---------
// Weights in padded stride-52 rows: 12 LDS.128 + 1 LDS.64 per k.
__global__ __launch_bounds__(128) void mlp_tail_kernel(
    const float* __restrict__ W2, const float* __restrict__ b2,
    const float* __restrict__ W3, const float* __restrict__ b3,
    const float* __restrict__ W4, const float* __restrict__ b4)
{
    __shared__ __align__(16) float sW2[50 * 52];
    __shared__ __align__(16) float sW3[50 * 52];
    __shared__ __align__(16) float sW4[304];
    __shared__ float sB2[56], sB3[56], sB4[8];

    int tid = threadIdx.x;
    for (int i = tid; i < 50 * 52; i += 128) {
        int r = i / 52, c = i - r * 52;
        float v2 = (c < 50) ? W2[r * 50 + c] : 0.f;
        float v3 = (c < 50) ? W3[r * 50 + c] : 0.f;
        sW2[i] = v2; sW3[i] = v3;
    }
    for (int i = tid; i < 300;  i += 128) sW4[i] = W4[i];
    if (tid < 50) { sB2[tid] = b2[tid]; sB3[tid] = b3[tid]; }
    if (tid < 6)  sB4[tid] = b4[tid];
    __syncthreads();

    int node = blockIdx.x * 128 + tid;
    if (node >= N_NODES) return;

    float xa[50];
    const float* xin = &g_x1[(size_t)node * H_DIM];
#pragma unroll
    for (int j = 0; j < 25; j++) {
        float2 v = *(const float2*)(xin + 2 * j);
        xa[2 * j] = v.x; xa[2 * j + 1] = v.y;
    }

    // layer 2
    {
        ull acc[25];
#pragma unroll
        for (int j = 0; j < 25; j++) acc[j] = 0ull;
#pragma unroll
        for (int k = 0; k < 50; k++) {
            ull f2 = pack2(xa[k], xa[k]);
            const ull* wr = (const ull*)&sW2[k * 52];
#pragma unroll
            for (int j = 0; j < 12; j++) {
                ulonglong2 w2 = *(const ulonglong2*)(wr + 2 * j);   // LDS.128
                acc[2 * j]     = ffma2(f2, w2.x, acc[2 * j]);
                acc[2 * j + 1] = ffma2(f2, w2.y, acc[2 * j + 1]);
            }
            acc[24] = ffma2(f2, wr[24], acc[24]);                   // LDS.64
        }
#pragma unroll
        for (int j = 0; j < 25; j++) {
            float a, b; unpack2(acc[j], a, b);
            xa[2 * j]     = fmaxf(a + sB2[2 * j],     0.f);
            xa[2 * j + 1] = fmaxf(b + sB2[2 * j + 1], 0.f);
        }
    }
    // layer 3
    {
        ull acc[25];
#pragma unroll
        for (int j = 0; j < 25; j++) acc[j] = 0ull;
#pragma unroll
        for (int k = 0; k < 50; k++) {
            ull f2 = pack2(xa[k], xa[k]);
            const ull* wr = (const ull*)&sW3[k * 52];
#pragma unroll
            for (int j = 0; j < 12; j++) {
                ulonglong2 w2 = *(const ulonglong2*)(wr + 2 * j);   // LDS.128
                acc[2 * j]     = ffma2(f2, w2.x, acc[2 * j]);
                acc[2 * j + 1] = ffma2(f2, w2.y, acc[2 * j + 1]);
            }
            acc[24] = ffma2(f2, wr[24], acc[24]);                   // LDS.64
        }
#pragma unroll
        for (int j = 0; j < 25; j++) {
            float a, b; unpack2(acc[j], a, b);
            xa[2 * j]     = fmaxf(a + sB3[2 * j],     0.f);
            xa[2 * j + 1] = fmaxf(b + sB3[2 * j + 1], 0.f);
        }
    }
    // layer 4 -> z, plus exp tables for KENN layer 0 (buffer 0)
    {
        ull acc[3] = {0ull, 0ull, 0ull};
#pragma unroll
        for (int k = 0; k < 50; k++) {
            ull f2 = pack2(xa[k], xa[k]);
            const float* wr = &sW4[k * 6];
#pragma unroll
            for (int j = 0; j < 3; j++)
                acc[j] = ffma2(f2, *(const ull*)(wr + 2 * j), acc[j]);
        }
        float zr[6];
#pragma unroll
        for (int j = 0; j < 3; j++) {
            float a, b; unpack2(acc[j], a, b);
            zr[2 * j]     = a + sB4[2 * j];
            zr[2 * j + 1] = b + sB4[2 * j + 1];
        }
        float* zp = &g_z[(size_t)node * 8];
        *(float4*)zp       = make_float4(zr[0], zr[1], zr[2], zr[3]);
        *(float2*)(zp + 4) = make_float2(zr[4], zr[5]);

        float em[6], ep[6];
#pragma unroll
        for (int c = 0; c < 6; c++) { ep[c] = __expf(zr[c]); em[c] = __expf(-zr[c]); }
        float* e1 = &g_EmB[(size_t)node * 8];
        float* e2 = &g_EpB[(size_t)node * 8];
        *(float4*)e1       = make_float4(em[0], em[1], em[2], em[3]);
        *(float2*)(e1 + 4) = make_float2(em[4], em[5]);
        *(float4*)e2       = make_float4(ep[0], ep[1], ep[2], ep[3]);
        *(float2*)(e2 + 4) = make_float2(ep[4], ep[5]);
    }
}

// ---------------- K3: KENN layer, pull-based (no atomics) -----------------
__global__ __launch_bounds__(256) void layer_kernel(
    const float* __restrict__ cw, int rd, int last, float* __restrict__ out)
{
    int n = blockIdx.x * 256 + threadIdx.x;
    if (n >= N_NODES) return;

    const float* EmR = g_EmB + (size_t)rd * N_NODES * 8;
    const float* EpR = g_EpB + (size_t)rd * N_NODES * 8;
    float* EmW = g_EmB + (size_t)(rd ^ 1) * N_NODES * 8;
    float* EpW = g_EpB + (size_t)(rd ^ 1) * N_NODES * 8;

    float4 u4 = *(const float4*)(EmR + (size_t)n * 8);
    float2 u2 = *(const float2*)(EmR + (size_t)n * 8 + 4);
    float4 w4 = *(const float4*)(EpR + (size_t)n * 8);
    float2 w2 = *(const float2*)(EpR + (size_t)n * 8 + 4);
    float u[6] = {u4.x, u4.y, u4.z, u4.w, u2.x, u2.y};
    float w[6] = {w4.x, w4.y, w4.z, w4.w, w2.x, w2.y};

    float c[6];
#pragma unroll
    for (int i = 0; i < 6; i++) c[i] = __ldg(cw + i);

    float acc[6] = {0.f, 0.f, 0.f, 0.f, 0.f, 0.f};

    int dx = min(g_cX[n], CAP);
    int dy = min(g_cY[n], CAP);

#pragma unroll 2
    for (int i = 0; i < dx; i++) {
        float2 rec = g_LX[(size_t)i * N_NODES + n];
        int b = __float_as_int(rec.x);
        float v = rec.y;
        const float* tb = EpR + (size_t)b * 8;
        float4 o4 = *(const float4*)tb;
        float2 o2 = *(const float2*)(tb + 4);
        acc[0] -= c[0] * u[0] * rcpa(u[0] + v + o4.x);
        acc[1] -= c[1] * u[1] * rcpa(u[1] + v + o4.y);
        acc[2] -= c[2] * u[2] * rcpa(u[2] + v + o4.z);
        acc[3] -= c[3] * u[3] * rcpa(u[3] + v + o4.w);
        acc[4] -= c[4] * u[4] * rcpa(u[4] + v + o2.x);
        acc[5] -= c[5] * u[5] * rcpa(u[5] + v + o2.y);
    }
#pragma unroll 2
    for (int i = 0; i < dy; i++) {
        float2 rec = g_LY[(size_t)i * N_NODES + n];
        int a = __float_as_int(rec.x);
        float v = rec.y;
        const float* ta = EmR + (size_t)a * 8;
        float4 o4 = *(const float4*)ta;
        float2 o2 = *(const float2*)(ta + 4);
        acc[0] += c[0] * w[0] * rcpa(o4.x + v + w[0]);
        acc[1] += c[1] * w[1] * rcpa(o4.y + v + w[1]);
        acc[2] += c[2] * w[2] * rcpa(o4.z + v + w[2]);
        acc[3] += c[3] * w[3] * rcpa(o4.w + v + w[3]);
        acc[4] += c[4] * w[4] * rcpa(o2.x + v + w[4]);
        acc[5] += c[5] * w[5] * rcpa(o2.y + v + w[5]);
    }

    float* zp = &g_z[(size_t)n * 8];
    float4 z4 = *(const float4*)zp;
    float2 z2 = *(const float2*)(zp + 4);
    float zn[6] = {z4.x + acc[0], z4.y + acc[1], z4.z + acc[2],
                   z4.w + acc[3], z2.x + acc[4], z2.y + acc[5]};
    *(float4*)zp       = make_float4(zn[0], zn[1], zn[2], zn[3]);
    *(float2*)(zp + 4) = make_float2(zn[4], zn[5]);

    if (!last) {
        float em[6], ep[6];
#pragma unroll
        for (int k = 0; k < 6; k++) { ep[k] = __expf(zn[k]); em[k] = __expf(-zn[k]); }
        float* e1 = EmW + (size_t)n * 8;
        float* e2 = EpW + (size_t)n * 8;
        *(float4*)e1       = make_float4(em[0], em[1], em[2], em[3]);
        *(float2*)(e1 + 4) = make_float2(em[4], em[5]);
        *(float4*)e2       = make_float4(ep[0], ep[1], ep[2], ep[3]);
        *(float2*)(e2 + 4) = make_float2(ep[4], ep[5]);
    } else {
        float mx = zn[0];
#pragma unroll
        for (int k = 1; k < 6; k++) mx = fmaxf(mx, zn[k]);
        float e[6], s = 0.f;
#pragma unroll
        for (int k = 0; k < 6; k++) { e[k] = __expf(zn[k] - mx); s += e[k]; }
        float inv = rcpa(s);
        float* op = out + (size_t)n * 6;
        *(float2*)op       = make_float2(e[0] * inv, e[1] * inv);
        *(float2*)(op + 2) = make_float2(e[2] * inv, e[3] * inv);
        *(float2*)(op + 4) = make_float2(e[4] * inv, e[5] * inv);
    }
}

// ---------------- launcher ------------------------------------------------
extern "C" void kernel_launch(void* const* d_in, const int* in_sizes, int n_in,
                              void* d_out, int out_size)
{
    const float* F   = (const float*)d_in[0];
    const float* rel = (const float*)d_in[1];
    const int*   sx  = (const int*)d_in[2];
    const int*   sy  = (const int*)d_in[3];
    const float* W1  = (const float*)d_in[4];
    const float* b1  = (const float*)d_in[5];
    const float* W2  = (const float*)d_in[6];
    const float* b2  = (const float*)d_in[7];
    const float* W3  = (const float*)d_in[8];
    const float* b3  = (const float*)d_in[9];
    const float* W4  = (const float*)d_in[10];
    const float* b4  = (const float*)d_in[11];
    const float* cw  = (const float*)d_in[12];
    float* out = (float*)d_out;

    w1split_kernel <<<(128 * NT * 8 * 4 + 255) / 256, 256>>>(W1);     // 0
    zero_kernel    <<<(N_NODES + 255) / 256, 256>>>();                // 1
    prep_kernel    <<<(M_EDGES + 255) / 256, 256>>>(rel, sx, sy);     // 2
    gemm1_mma_kernel<<<(N_NODES + 255) / 256, 256>>>(F, b1);          // 3 <- ncu slot
    mlp_tail_kernel<<<(N_NODES + 127) / 128, 128>>>(W2, b2, W3, b3, W4, b4); // 4

    int grid = (N_NODES + 255) / 256;
    layer_kernel<<<grid, 256>>>(cw + 0,  0, 0, out);                  // 5
    layer_kernel<<<grid, 256>>>(cw + 6,  1, 0, out);                  // 6
    layer_kernel<<<grid, 256>>>(cw + 12, 0, 1, out);                  // 7
}